// round 10
// baseline (speedup 1.0000x reference)
#include <cuda_runtime.h>
#include <cuda_bf16.h>
#include <stdint.h>
#include <math.h>

#define NN 10000
#define NE 160000

// ---------------- device scratch (static, allocation-free) ----------------
__device__ float g_t[NN * 16];
__device__ float g_qW[NN * 8];
// transposed, split weights [N, K] bf16
__device__ __nv_bfloat16 g_w1k_h[128 * 32], g_w1k_l[128 * 32];
__device__ __nv_bfloat16 g_w1v_h[128 * 32], g_w1v_l[128 * 32];
__device__ __nv_bfloat16 g_w2k_h[128 * 128], g_w2k_l[128 * 128];
__device__ __nv_bfloat16 g_w2v_h[128 * 128], g_w2v_l[128 * 128];
__device__ __nv_bfloat16 g_w3k_h[512 * 128], g_w3k_l[512 * 128];
__device__ __nv_bfloat16 g_w3v_h[1024 * 128], g_w3v_l[1024 * 128];
// fp32 tail
__device__ float g_vbuf[(size_t)NE * 16];
__device__ float g_logit[NE];
__device__ float g_m[NN];
__device__ float g_z[NN];
__device__ float g_agg[NN * 16];
__device__ float g_colsum[64];
__device__ float g_colsumsq[64];
__device__ float g_outpre[NN * 64];

// ---------------- helpers ----------------
__device__ __forceinline__ void atomicMaxF(float* addr, float v) {
    if (v >= 0.f)
        atomicMax((int*)addr, __float_as_int(v));
    else
        atomicMin((unsigned int*)addr, __float_as_uint(v));
}

__device__ __forceinline__ uint32_t smem_u32(const void* p) {
    uint32_t a;
    asm("{ .reg .u64 t; cvta.to.shared.u64 t, %1; cvt.u32.u64 %0, t; }" : "=r"(a) : "l"(p));
    return a;
}

__device__ __forceinline__ void split2(float x, __nv_bfloat16& h, __nv_bfloat16& l) {
    h = __float2bfloat16(x);
    l = __float2bfloat16(x - __bfloat162float(h));
}

__device__ __forceinline__ void ldm4(uint32_t* r, uint32_t addr) {
    asm volatile("ldmatrix.sync.aligned.m8n8.x4.shared.b16 {%0,%1,%2,%3}, [%4];"
                 : "=r"(r[0]), "=r"(r[1]), "=r"(r[2]), "=r"(r[3]) : "r"(addr));
}

__device__ __forceinline__ void mma16816(float* c, const uint32_t* a, const uint32_t* b) {
    asm volatile(
        "mma.sync.aligned.m16n8k16.row.col.f32.bf16.bf16.f32 "
        "{%0,%1,%2,%3}, {%4,%5,%6,%7}, {%8,%9}, {%0,%1,%2,%3};"
        : "+f"(c[0]), "+f"(c[1]), "+f"(c[2]), "+f"(c[3])
        : "r"(a[0]), "r"(a[1]), "r"(a[2]), "r"(a[3]), "r"(b[0]), "r"(b[1]));
}

// 3-term split MMA, 32x32 warp tile, fragments hoisted, pass-ordered issue:
// per k-step: 8 ldsm -> 24 mma; same-acc MMAs are 8 tiles apart.
template <int KS, int PITCH>
__device__ __forceinline__ void mma_block(
    uint32_t aH, uint32_t aL, uint32_t bH, uint32_t bL,
    int lane, int wm, int wn, float c[2][4][4])
{
    #pragma unroll
    for (int kk = 0; kk < KS; kk++) {
        uint32_t ah[2][4], al[2][4], bh[2][4], bl[2][4];
        #pragma unroll
        for (int mt = 0; mt < 2; mt++) {
            int row = wm + mt * 16 + (lane & 15);
            uint32_t off = (uint32_t)(row * PITCH + kk * 16 + 8 * (lane >> 4)) << 1;
            ldm4(ah[mt], aH + off);
            ldm4(al[mt], aL + off);
        }
        #pragma unroll
        for (int np = 0; np < 2; np++) {
            int row = wn + np * 16 + ((lane >> 4) << 3) + (lane & 7);
            uint32_t off = (uint32_t)(row * PITCH + kk * 16 + 8 * ((lane >> 3) & 1)) << 1;
            ldm4(bh[np], bH + off);
            ldm4(bl[np], bL + off);
        }
        #pragma unroll
        for (int p = 0; p < 3; p++)
            #pragma unroll
            for (int mt = 0; mt < 2; mt++)
                #pragma unroll
                for (int nt = 0; nt < 4; nt++) {
                    const uint32_t* af = (p == 2) ? al[mt] : ah[mt];
                    uint32_t bb[2];
                    if (p == 1) {
                        bb[0] = bl[nt >> 1][(nt & 1) * 2];
                        bb[1] = bl[nt >> 1][(nt & 1) * 2 + 1];
                    } else {
                        bb[0] = bh[nt >> 1][(nt & 1) * 2];
                        bb[1] = bh[nt >> 1][(nt & 1) * 2 + 1];
                    }
                    mma16816(c[mt][nt], af, bb);
                }
    }
}

// bias + relu + split-store fragments into a [128][136] hi/lo smem tile
__device__ __forceinline__ void epi_split_store(
    float c[2][4][4], const float* __restrict__ bias,
    __nv_bfloat16* Dh, __nv_bfloat16* Dl, int lane, int wm, int wn)
{
    constexpr int P = 136;
    #pragma unroll
    for (int mt = 0; mt < 2; mt++) {
        int r0 = wm + mt * 16 + (lane >> 2);
        #pragma unroll
        for (int nt = 0; nt < 4; nt++) {
            int col = wn + nt * 8 + (lane & 3) * 2;
            float b0 = __ldg(bias + col), b1 = __ldg(bias + col + 1);
            float v0 = fmaxf(c[mt][nt][0] + b0, 0.f);
            float v1 = fmaxf(c[mt][nt][1] + b1, 0.f);
            float v2 = fmaxf(c[mt][nt][2] + b0, 0.f);
            float v3 = fmaxf(c[mt][nt][3] + b1, 0.f);
            __nv_bfloat16 h0, l0, h1, l1;
            split2(v0, h0, l0); split2(v1, h1, l1);
            *(__nv_bfloat162*)&Dh[r0 * P + col] = __nv_bfloat162(h0, h1);
            *(__nv_bfloat162*)&Dl[r0 * P + col] = __nv_bfloat162(l0, l1);
            split2(v2, h0, l0); split2(v3, h1, l1);
            *(__nv_bfloat162*)&Dh[(r0 + 8) * P + col] = __nv_bfloat162(h0, h1);
            *(__nv_bfloat162*)&Dl[(r0 + 8) * P + col] = __nv_bfloat162(l0, l1);
        }
    }
}

// ---------------- weight prep ----------------
__device__ __forceinline__ void wsplit_one(const float* src, __nv_bfloat16* dh,
                                           __nv_bfloat16* dl, int K, int N, int i) {
    int n = i / K, k = i % K;
    __nv_bfloat16 h, l;
    split2(src[k * N + n], h, l);
    dh[i] = h;
    dl[i] = l;
}

__global__ void wsplit_all(const float* __restrict__ Wk1, const float* __restrict__ Wv1,
                           const float* __restrict__ Wk2, const float* __restrict__ Wv2,
                           const float* __restrict__ Wk3, const float* __restrict__ Wv3)
{
    int i = blockIdx.x * 256 + threadIdx.x;
    if (i < 4096) { wsplit_one(Wk1, g_w1k_h, g_w1k_l, 32, 128, i); return; }
    i -= 4096;
    if (i < 4096) { wsplit_one(Wv1, g_w1v_h, g_w1v_l, 32, 128, i); return; }
    i -= 4096;
    if (i < 16384) { wsplit_one(Wk2, g_w2k_h, g_w2k_l, 128, 128, i); return; }
    i -= 16384;
    if (i < 16384) { wsplit_one(Wv2, g_w2v_h, g_w2v_l, 128, 128, i); return; }
    i -= 16384;
    if (i < 65536) { wsplit_one(Wk3, g_w3k_h, g_w3k_l, 128, 512, i); return; }
    i -= 65536;
    if (i < 131072) { wsplit_one(Wv3, g_w3v_h, g_w3v_l, 128, 1024, i); }
}

// ---------------- full MLP chain + contraction (device body), 512 threads ----------------
// NOUT=16/NB=8: V path;  NOUT=8/NB=4: K path (logits)
template <int NOUT, int NB>
__device__ __forceinline__ void chain_body(
    char* sm,
    const float* __restrict__ edge_data,
    const __nv_bfloat16* __restrict__ W1h, const __nv_bfloat16* __restrict__ W1l,
    const float* __restrict__ b1,
    const __nv_bfloat16* __restrict__ W2h, const __nv_bfloat16* __restrict__ W2l,
    const float* __restrict__ b2,
    const __nv_bfloat16* __restrict__ W3h, const __nv_bfloat16* __restrict__ W3l,
    const float* __restrict__ b3,
    const int* __restrict__ ei, const float* __restrict__ sh)
{
    constexpr int NT = 512;
    constexpr int P = 136, PA = 40;
    constexpr int NTOT = NB * 128;
    constexpr int NSLOT = (NOUT == 16) ? 4 : 2;
    constexpr int PP = NOUT + 1;
    __nv_bfloat16* H1h = (__nv_bfloat16*)(sm);
    __nv_bfloat16* H1l = (__nv_bfloat16*)(sm + 34816);
    __nv_bfloat16* WBh = (__nv_bfloat16*)(sm + 69632);
    __nv_bfloat16* WBl = (__nv_bfloat16*)(sm + 104448);
    __nv_bfloat16* H2h = (__nv_bfloat16*)(sm + 139264);
    __nv_bfloat16* H2l = (__nv_bfloat16*)(sm + 174080);
    __nv_bfloat16* EAh = (__nv_bfloat16*)(sm + 139264);           // phase-1 scratch
    __nv_bfloat16* EAl = (__nv_bfloat16*)(sm + 149504);
    __nv_bfloat16* W1sh = (__nv_bfloat16*)(sm + 159744);
    __nv_bfloat16* W1sl = (__nv_bfloat16*)(sm + 169984);
    float* u_s = (float*)sm;
    float* part = (float*)(sm + 33280);
    float* bs = (float*)(sm + 208896);

    const int tid = threadIdx.x, lane = tid & 31, warp = tid >> 5;
    const int m0 = blockIdx.x * 128;
    const int wm = (warp >> 2) * 32, wn = (warp & 3) * 32;

    float c[2][4][4];

    // ===== phase 1: h1 = relu(edge @ W1^T + b1) =====
    for (int i = tid; i < 128 * 8; i += NT) {
        int row = i >> 3, c4 = (i & 7) * 4;
        float4 v = *(const float4*)(edge_data + (size_t)(m0 + row) * 32 + c4);
        __nv_bfloat16 h[4], l[4];
        split2(v.x, h[0], l[0]); split2(v.y, h[1], l[1]);
        split2(v.z, h[2], l[2]); split2(v.w, h[3], l[3]);
        *(uint2*)&EAh[row * PA + c4] = *(uint2*)h;
        *(uint2*)&EAl[row * PA + c4] = *(uint2*)l;
    }
    for (int i = tid; i < 128 * 4; i += NT) {
        int row = i >> 2, c8 = (i & 3) * 8;
        *(uint4*)&W1sh[row * PA + c8] = ((const uint4*)W1h)[i];
        *(uint4*)&W1sl[row * PA + c8] = ((const uint4*)W1l)[i];
    }
    __syncthreads();

    #pragma unroll
    for (int mt = 0; mt < 2; mt++)
        #pragma unroll
        for (int nt = 0; nt < 4; nt++)
            #pragma unroll
            for (int j = 0; j < 4; j++) c[mt][nt][j] = 0.f;
    mma_block<2, PA>(smem_u32(EAh), smem_u32(EAl), smem_u32(W1sh), smem_u32(W1sl),
                     lane, wm, wn, c);
    epi_split_store(c, b1, H1h, H1l, lane, wm, wn);

    // ===== phase 2: h2 = relu(h1 @ W2^T + b2) =====
    for (int i = tid; i < 128 * 16; i += NT) {
        int row = i >> 4, c8 = (i & 15) * 8;
        *(uint4*)&WBh[row * P + c8] = ((const uint4*)W2h)[i];
        *(uint4*)&WBl[row * P + c8] = ((const uint4*)W2l)[i];
    }
    __syncthreads();

    #pragma unroll
    for (int mt = 0; mt < 2; mt++)
        #pragma unroll
        for (int nt = 0; nt < 4; nt++)
            #pragma unroll
            for (int j = 0; j < 4; j++) c[mt][nt][j] = 0.f;
    mma_block<8, P>(smem_u32(H1h), smem_u32(H1l), smem_u32(WBh), smem_u32(WBl),
                    lane, wm, wn, c);
    epi_split_store(c, b2, H2h, H2l, lane, wm, wn);
    __syncthreads();   // all warps done reading h1 (frees region for u_s) and writing h2

    // ===== phase 3: layer-3 GEMM streamed over n-blocks, fused contraction =====
    for (int i = tid; i < 128 * 64; i += NT) {
        int row = i >> 6, as = i & 63;
        int e = m0 + row;
        int src = ei[e];
        u_s[row * 65 + as] = g_t[src * 16 + (as >> 2)] * sh[e * 4 + (as & 3)] * 0.125f;
    }
    for (int i = tid; i < NTOT; i += NT) bs[i] = b3[i];

    float loc[4][NSLOT];
    #pragma unroll
    for (int s = 0; s < 4; s++)
        #pragma unroll
        for (int j = 0; j < NSLOT; j++) loc[s][j] = 0.f;

    const uint32_t sH2h = smem_u32(H2h), sH2l = smem_u32(H2l);
    const uint32_t sWBh = smem_u32(WBh), sWBl = smem_u32(WBl);

    for (int nb = 0; nb < NB; nb++) {
        __syncthreads();
        const uint4* gBh = (const uint4*)(W3h + (size_t)nb * 128 * 128);
        const uint4* gBl = (const uint4*)(W3l + (size_t)nb * 128 * 128);
        for (int i = tid; i < 128 * 16; i += NT) {
            int row = i >> 4, c8 = (i & 15) * 8;
            *(uint4*)&WBh[row * P + c8] = gBh[i];
            *(uint4*)&WBl[row * P + c8] = gBl[i];
        }
        __syncthreads();

        #pragma unroll
        for (int mt = 0; mt < 2; mt++)
            #pragma unroll
            for (int nt = 0; nt < 4; nt++)
                #pragma unroll
                for (int j = 0; j < 4; j++) c[mt][nt][j] = 0.f;
        mma_block<8, P>(sH2h, sH2l, sWBh, sWBl, lane, wm, wn, c);

        #pragma unroll
        for (int mt = 0; mt < 2; mt++) {
            int r = wm + mt * 16 + (lane >> 2);
            #pragma unroll
            for (int nt = 0; nt < 4; nt++) {
                int colb = nb * 128 + wn + nt * 8;
                int as = (NOUT == 16) ? (colb >> 4) : (colb >> 3);
                int obi = (NOUT == 16) ? ((nt & 1) * 2) : 0;
                float ur = u_s[r * 65 + as];
                float ur8 = u_s[(r + 8) * 65 + as];
                loc[mt * 2][obi]         += c[mt][nt][0] * ur;
                loc[mt * 2][obi + 1]     += c[mt][nt][1] * ur;
                loc[mt * 2 + 1][obi]     += c[mt][nt][2] * ur8;
                loc[mt * 2 + 1][obi + 1] += c[mt][nt][3] * ur8;
            }
        }
    }

    // per-warp partials -> smem (4 column-warps per row set)
    {
        int wi = warp & 3;
        #pragma unroll
        for (int s = 0; s < 4; s++) {
            int row = wm + (s >> 1) * 16 + (s & 1) * 8 + (lane >> 2);
            #pragma unroll
            for (int j = 0; j < NSLOT; j++) {
                int ob = (lane & 3) * 2 + (j & 1) + (j >> 1) * 8;
                part[(wi * 128 + row) * PP + ob] = loc[s][j];
            }
        }
    }
    __syncthreads();

    if (NOUT == 16) {
        for (int idx = tid; idx < 128 * 16; idx += NT) {
            int row = idx >> 4, ob = idx & 15;
            float s = part[row * PP + ob] + part[(128 + row) * PP + ob]
                    + part[(256 + row) * PP + ob] + part[(384 + row) * PP + ob];
            float bt = 0.f;
            #pragma unroll
            for (int as = 0; as < 64; as++) bt = fmaf(u_s[row * 65 + as], bs[as * 16 + ob], bt);
            g_vbuf[(size_t)(m0 + row) * 16 + ob] = s + bt;
        }
    } else {
        for (int idx = tid; idx < 128 * 8; idx += NT) {
            int row = idx >> 3, b = idx & 7;
            float s = part[row * PP + b] + part[(128 + row) * PP + b]
                    + part[(256 + row) * PP + b] + part[(384 + row) * PP + b];
            float bt = 0.f;
            #pragma unroll
            for (int as = 0; as < 64; as++) bt = fmaf(u_s[row * 65 + as], bs[as * 8 + b], bt);
            part[row * PP + b] = s + bt;
        }
        __syncthreads();
        if (tid < 128) {
            int e = m0 + tid;
            int dst = ei[NE + e];
            float lp = 0.f;
            #pragma unroll
            for (int b = 0; b < 8; b++) lp += part[tid * PP + b] * g_qW[dst * 8 + b];
            g_logit[e] = lp;
            atomicMaxF(&g_m[dst], lp);
        }
    }
}

// one kernel runs the V chain then the K chain on the same 128 edges
__global__ __launch_bounds__(512, 1) void chain_both(
    const float* __restrict__ edge_data,
    const __nv_bfloat16* __restrict__ Wv1h, const __nv_bfloat16* __restrict__ Wv1l,
    const float* __restrict__ bv1,
    const __nv_bfloat16* __restrict__ Wv2h, const __nv_bfloat16* __restrict__ Wv2l,
    const float* __restrict__ bv2,
    const __nv_bfloat16* __restrict__ Wv3h, const __nv_bfloat16* __restrict__ Wv3l,
    const float* __restrict__ bv3,
    const __nv_bfloat16* __restrict__ Wk1h, const __nv_bfloat16* __restrict__ Wk1l,
    const float* __restrict__ bk1,
    const __nv_bfloat16* __restrict__ Wk2h, const __nv_bfloat16* __restrict__ Wk2l,
    const float* __restrict__ bk2,
    const __nv_bfloat16* __restrict__ Wk3h, const __nv_bfloat16* __restrict__ Wk3l,
    const float* __restrict__ bk3,
    const int* __restrict__ ei, const float* __restrict__ sh)
{
    extern __shared__ char sm[];
    chain_body<16, 8>(sm, edge_data, Wv1h, Wv1l, bv1, Wv2h, Wv2l, bv2,
                      Wv3h, Wv3l, bv3, ei, sh);
    __syncthreads();
    chain_body<8, 4>(sm, edge_data, Wk1h, Wk1l, bk1, Wk2h, Wk2l, bk2,
                     Wk3h, Wk3l, bk3, ei, sh);
}

// ---------------- init ----------------
__global__ void init_kernel() {
    int i = blockIdx.x * 256 + threadIdx.x;
    if (i < NN) { g_m[i] = -INFINITY; g_z[i] = 0.f; }
    if (i < NN * 16) g_agg[i] = 0.f;
    if (i < 64) { g_colsum[i] = 0.f; g_colsumsq[i] = 0.f; }
}

// ---------------- node linears ----------------
__global__ __launch_bounds__(128) void node_kernel(
    const float* __restrict__ node_data, const float* __restrict__ W_input,
    const float* __restrict__ W_query, const float* __restrict__ W_dot)
{
    __shared__ float Wi[64 * 16];
    __shared__ float Wq[16 * 8];
    __shared__ float Wd[64];
    __shared__ float tsh[8][16];
    __shared__ float qsh[8][8];
    int tid = threadIdx.x;
    for (int i = tid; i < 1024; i += 128) Wi[i] = W_input[i];
    if (tid < 128) Wq[tid] = W_query[tid];
    if (tid < 64) Wd[tid] = W_dot[tid];
    __syncthreads();

    int n_loc = tid >> 4, c = tid & 15;
    int n = blockIdx.x * 8 + n_loc;
    float tv = 0.f;
    if (n < NN) {
        const float* nd = node_data + (size_t)n * 64;
        #pragma unroll 8
        for (int i = 0; i < 64; i++) tv += nd[i] * Wi[i * 16 + c];
        tv *= 0.125f;
        g_t[n * 16 + c] = tv;
    }
    tsh[n_loc][c] = tv;
    __syncthreads();

    if (tid < 64) {
        int nl = tid >> 3, b = tid & 7;
        float qv = 0.f;
        #pragma unroll
        for (int a = 0; a < 16; a++) qv += tsh[nl][a] * Wq[a * 8 + b];
        qsh[nl][b] = qv * 0.25f;
    }
    __syncthreads();
    if (tid < 64) {
        int nl = tid >> 3, b = tid & 7;
        int n2 = blockIdx.x * 8 + nl;
        if (n2 < NN) {
            float s = 0.f;
            #pragma unroll
            for (int a = 0; a < 8; a++) s += qsh[nl][a] * Wd[a * 8 + b];
            g_qW[n2 * 8 + b] = s * 0.125f;
        }
    }
}

// ---------------- softmax numerator + segment sums ----------------
__global__ void attn_agg_kernel(const int* __restrict__ ei)
{
    int e = blockIdx.x * 256 + threadIdx.x;
    if (e >= NE) return;
    int dst = ei[NE + e];
    float p = expf(g_logit[e] - g_m[dst]);
    atomicAdd(&g_z[dst], p);
    const float* v = g_vbuf + (size_t)e * 16;
    float* agg = g_agg + dst * 16;
    #pragma unroll
    for (int c = 0; c < 16; c++) atomicAdd(&agg[c], p * v[c]);
}

// ---------------- output linear + residual + BN stats ----------------
__global__ __launch_bounds__(256) void out_stats_kernel(
    const float* __restrict__ node_data, const float* __restrict__ W_output)
{
    __shared__ float Wsh[16 * 64];
    __shared__ float red[256];
    int tid = threadIdx.x;
    for (int i = tid; i < 1024; i += 256) Wsh[i] = W_output[i];
    __syncthreads();

    int c = tid & 63;
    int r = tid >> 6;
    int n0 = blockIdx.x * 64;
    float lsum = 0.f, lsq = 0.f;
    for (int i = 0; i < 16; i++) {
        int n = n0 + r + i * 4;
        if (n < NN) {
            float zz = g_z[n];
            float inv = zz > 0.f ? 0.25f / zz : 0.f;
            float o = 0.f;
            const float* agg = g_agg + n * 16;
            #pragma unroll
            for (int j = 0; j < 16; j++) o += agg[j] * Wsh[j * 64 + c];
            o = o * inv + node_data[(size_t)n * 64 + c];
            g_outpre[(size_t)n * 64 + c] = o;
            lsum += o;
            lsq += o * o;
        }
    }
    red[tid] = lsum;
    __syncthreads();
    if (r == 0) atomicAdd(&g_colsum[c], red[c] + red[64 + c] + red[128 + c] + red[192 + c]);
    __syncthreads();
    red[tid] = lsq;
    __syncthreads();
    if (r == 0) atomicAdd(&g_colsumsq[c], red[c] + red[64 + c] + red[128 + c] + red[192 + c]);
}

// ---------------- batchnorm finalize ----------------
__global__ void bn_kernel(const float* __restrict__ bnw, const float* __restrict__ bnb,
                          float* __restrict__ out)
{
    int i = blockIdx.x * 256 + threadIdx.x;
    if (i >= NN * 64) return;
    int c = i & 63;
    const float invN = 1.f / NN;
    float mean = g_colsum[c] * invN;
    float var = g_colsumsq[c] * invN - mean * mean;
    out[i] = (g_outpre[i] - mean) * rsqrtf(var + 1e-5f) * bnw[c] + bnb[c];
}

// ---------------- launch ----------------
extern "C" void kernel_launch(void* const* d_in, const int* in_sizes, int n_in,
                              void* d_out, int out_size)
{
    const float* node_data = (const float*)d_in[0];
    const int*   edge_index = (const int*)d_in[1];
    const float* edge_data = (const float*)d_in[2];
    const float* edge_sh   = (const float*)d_in[3];
    const float* W_input = (const float*)d_in[4];
    const float* W_query = (const float*)d_in[5];
    const float* W_dot   = (const float*)d_in[6];
    const float* W_output = (const float*)d_in[7];
    const float* Wk1 = (const float*)d_in[8];
    const float* bk1 = (const float*)d_in[9];
    const float* Wk2 = (const float*)d_in[10];
    const float* bk2 = (const float*)d_in[11];
    const float* Wk3 = (const float*)d_in[12];
    const float* bk3 = (const float*)d_in[13];
    const float* Wv1 = (const float*)d_in[14];
    const float* bv1 = (const float*)d_in[15];
    const float* Wv2 = (const float*)d_in[16];
    const float* bv2 = (const float*)d_in[17];
    const float* Wv3 = (const float*)d_in[18];
    const float* bv3 = (const float*)d_in[19];
    const float* bn_weight = (const float*)d_in[20];
    const float* bn_bias   = (const float*)d_in[21];
    float* out = (float*)d_out;

    void *pw1kh, *pw1kl, *pw1vh, *pw1vl, *pw2kh, *pw2kl, *pw2vh, *pw2vl;
    void *pw3kh, *pw3kl, *pw3vh, *pw3vl;
    cudaGetSymbolAddress(&pw1kh, g_w1k_h); cudaGetSymbolAddress(&pw1kl, g_w1k_l);
    cudaGetSymbolAddress(&pw1vh, g_w1v_h); cudaGetSymbolAddress(&pw1vl, g_w1v_l);
    cudaGetSymbolAddress(&pw2kh, g_w2k_h); cudaGetSymbolAddress(&pw2kl, g_w2k_l);
    cudaGetSymbolAddress(&pw2vh, g_w2v_h); cudaGetSymbolAddress(&pw2vl, g_w2v_l);
    cudaGetSymbolAddress(&pw3kh, g_w3k_h); cudaGetSymbolAddress(&pw3kl, g_w3k_l);
    cudaGetSymbolAddress(&pw3vh, g_w3v_h); cudaGetSymbolAddress(&pw3vl, g_w3v_l);

    const int SMC = 208896 + 4096;   // 212992
    cudaFuncSetAttribute(chain_both, cudaFuncAttributeMaxDynamicSharedMemorySize, SMC);

    init_kernel<<<(NE + 255) / 256, 256>>>();                                   // 0
    wsplit_all<<<(237568 + 255) / 256, 256>>>(Wk1, Wv1, Wk2, Wv2, Wk3, Wv3);    // 1
    node_kernel<<<(NN + 7) / 8, 128>>>(node_data, W_input, W_query, W_dot);     // 2
    chain_both<<<NE / 128, 512, SMC>>>(                                         // 3
        edge_data,
        (const __nv_bfloat16*)pw1vh, (const __nv_bfloat16*)pw1vl, bv1,
        (const __nv_bfloat16*)pw2vh, (const __nv_bfloat16*)pw2vl, bv2,
        (const __nv_bfloat16*)pw3vh, (const __nv_bfloat16*)pw3vl, bv3,
        (const __nv_bfloat16*)pw1kh, (const __nv_bfloat16*)pw1kl, bk1,
        (const __nv_bfloat16*)pw2kh, (const __nv_bfloat16*)pw2kl, bk2,
        (const __nv_bfloat16*)pw3kh, (const __nv_bfloat16*)pw3kl, bk3,
        edge_index, edge_sh);

    attn_agg_kernel<<<(NE + 255) / 256, 256>>>(edge_index);                     // 4
    out_stats_kernel<<<(NN + 63) / 64, 256>>>(node_data, W_output);             // 5
    bn_kernel<<<(NN * 64 + 255) / 256, 256>>>(bn_weight, bn_bias, out);         // 6
}

// round 11
// speedup vs baseline: 1.0941x; 1.0941x over previous
#include <cuda_runtime.h>
#include <cuda_bf16.h>
#include <stdint.h>
#include <math.h>

#define NN 10000
#define NE 160000

// ---------------- device scratch (static, allocation-free) ----------------
__device__ float g_t[NN * 16];
__device__ float g_qW[NN * 8];
// transposed, split weights [N, K] bf16
__device__ __nv_bfloat16 g_w1k_h[128 * 32], g_w1k_l[128 * 32];
__device__ __nv_bfloat16 g_w1v_h[128 * 32], g_w1v_l[128 * 32];
__device__ __nv_bfloat16 g_w2k_h[128 * 128], g_w2k_l[128 * 128];
__device__ __nv_bfloat16 g_w2v_h[128 * 128], g_w2v_l[128 * 128];
__device__ __nv_bfloat16 g_w3k_h[512 * 128], g_w3k_l[512 * 128];
__device__ __nv_bfloat16 g_w3v_h[1024 * 128], g_w3v_l[1024 * 128];
// fp32 tail
__device__ float g_vbuf[(size_t)NE * 16];
__device__ float g_logit[NE];
__device__ float g_m[NN];
__device__ float g_z[NN];
__device__ float g_agg[NN * 16];
__device__ float g_colsum[64];
__device__ float g_colsumsq[64];
__device__ float g_outpre[NN * 64];

// ---------------- helpers ----------------
__device__ __forceinline__ void atomicMaxF(float* addr, float v) {
    if (v >= 0.f)
        atomicMax((int*)addr, __float_as_int(v));
    else
        atomicMin((unsigned int*)addr, __float_as_uint(v));
}

__device__ __forceinline__ uint32_t smem_u32(const void* p) {
    uint32_t a;
    asm("{ .reg .u64 t; cvta.to.shared.u64 t, %1; cvt.u32.u64 %0, t; }" : "=r"(a) : "l"(p));
    return a;
}

__device__ __forceinline__ void split2(float x, __nv_bfloat16& h, __nv_bfloat16& l) {
    h = __float2bfloat16(x);
    l = __float2bfloat16(x - __bfloat162float(h));
}

__device__ __forceinline__ void ldm4(uint32_t* r, uint32_t addr) {
    asm volatile("ldmatrix.sync.aligned.m8n8.x4.shared.b16 {%0,%1,%2,%3}, [%4];"
                 : "=r"(r[0]), "=r"(r[1]), "=r"(r[2]), "=r"(r[3]) : "r"(addr));
}

__device__ __forceinline__ void mma16816(float* c, const uint32_t* a, const uint32_t* b) {
    asm volatile(
        "mma.sync.aligned.m16n8k16.row.col.f32.bf16.bf16.f32 "
        "{%0,%1,%2,%3}, {%4,%5,%6,%7}, {%8,%9}, {%0,%1,%2,%3};"
        : "+f"(c[0]), "+f"(c[1]), "+f"(c[2]), "+f"(c[3])
        : "r"(a[0]), "r"(a[1]), "r"(a[2]), "r"(a[3]), "r"(b[0]), "r"(b[1]));
}

// 3-term split MMA with fragments hoisted across the passes (64x32 warp tile):
// per k-step: 12 ldsm -> 48 mma (Ah*Bh + Ah*Bl + Al*Bh into the same fp32 acc)
template <int KS, int PITCH>
__device__ __forceinline__ void mma_block(
    uint32_t aH, uint32_t aL, uint32_t bH, uint32_t bL,
    int lane, int wm, int wn, float c[4][4][4])
{
    #pragma unroll
    for (int kk = 0; kk < KS; kk++) {
        uint32_t ah[4][4], al[4][4], bh[2][4], bl[2][4];
        #pragma unroll
        for (int mt = 0; mt < 4; mt++) {
            int row = wm + mt * 16 + (lane & 15);
            uint32_t off = (uint32_t)(row * PITCH + kk * 16 + 8 * (lane >> 4)) << 1;
            ldm4(ah[mt], aH + off);
            ldm4(al[mt], aL + off);
        }
        #pragma unroll
        for (int np = 0; np < 2; np++) {
            int row = wn + np * 16 + ((lane >> 4) << 3) + (lane & 7);
            uint32_t off = (uint32_t)(row * PITCH + kk * 16 + 8 * ((lane >> 3) & 1)) << 1;
            ldm4(bh[np], bH + off);
            ldm4(bl[np], bL + off);
        }
        #pragma unroll
        for (int mt = 0; mt < 4; mt++)
            #pragma unroll
            for (int nt = 0; nt < 4; nt++) {
                uint32_t bbh[2] = { bh[nt >> 1][(nt & 1) * 2], bh[nt >> 1][(nt & 1) * 2 + 1] };
                uint32_t bbl[2] = { bl[nt >> 1][(nt & 1) * 2], bl[nt >> 1][(nt & 1) * 2 + 1] };
                mma16816(c[mt][nt], ah[mt], bbh);
                mma16816(c[mt][nt], ah[mt], bbl);
                mma16816(c[mt][nt], al[mt], bbh);
            }
    }
}

// bias + relu + split-store fragments into a [128][136] hi/lo smem tile
__device__ __forceinline__ void epi_split_store(
    float c[4][4][4], const float* __restrict__ bias,
    __nv_bfloat16* Dh, __nv_bfloat16* Dl, int lane, int wm, int wn)
{
    constexpr int P = 136;
    #pragma unroll
    for (int mt = 0; mt < 4; mt++) {
        int r0 = wm + mt * 16 + (lane >> 2);
        #pragma unroll
        for (int nt = 0; nt < 4; nt++) {
            int col = wn + nt * 8 + (lane & 3) * 2;
            float b0 = __ldg(bias + col), b1 = __ldg(bias + col + 1);
            float v0 = fmaxf(c[mt][nt][0] + b0, 0.f);
            float v1 = fmaxf(c[mt][nt][1] + b1, 0.f);
            float v2 = fmaxf(c[mt][nt][2] + b0, 0.f);
            float v3 = fmaxf(c[mt][nt][3] + b1, 0.f);
            __nv_bfloat16 h0, l0, h1, l1;
            split2(v0, h0, l0); split2(v1, h1, l1);
            *(__nv_bfloat162*)&Dh[r0 * P + col] = __nv_bfloat162(h0, h1);
            *(__nv_bfloat162*)&Dl[r0 * P + col] = __nv_bfloat162(l0, l1);
            split2(v2, h0, l0); split2(v3, h1, l1);
            *(__nv_bfloat162*)&Dh[(r0 + 8) * P + col] = __nv_bfloat162(h0, h1);
            *(__nv_bfloat162*)&Dl[(r0 + 8) * P + col] = __nv_bfloat162(l0, l1);
        }
    }
}

// register-prefetch helpers for a 128x128 bf16 hi/lo block (2048 uint4 each)
__device__ __forceinline__ void ldg_blk(const __nv_bfloat16* Bh, const __nv_bfloat16* Bl,
                                        int tid, uint4 ph[8], uint4 pl[8]) {
    const uint4* gh = (const uint4*)Bh;
    const uint4* gl = (const uint4*)Bl;
    #pragma unroll
    for (int r = 0; r < 8; r++) {
        ph[r] = __ldg(gh + tid + r * 256);
        pl[r] = __ldg(gl + tid + r * 256);
    }
}
__device__ __forceinline__ void sts_blk(__nv_bfloat16* WBh, __nv_bfloat16* WBl,
                                        int tid, const uint4 ph[8], const uint4 pl[8]) {
    #pragma unroll
    for (int r = 0; r < 8; r++) {
        int i = tid + r * 256;
        int row = i >> 4, c8 = (i & 15) * 8;
        *(uint4*)&WBh[row * 136 + c8] = ph[r];
        *(uint4*)&WBl[row * 136 + c8] = pl[r];
    }
}

// ---------------- weight prep ----------------
__device__ __forceinline__ void wsplit_one(const float* src, __nv_bfloat16* dh,
                                           __nv_bfloat16* dl, int K, int N, int i) {
    int n = i / K, k = i % K;
    __nv_bfloat16 h, l;
    split2(src[k * N + n], h, l);
    dh[i] = h;
    dl[i] = l;
}

__global__ void wsplit_all(const float* __restrict__ Wk1, const float* __restrict__ Wv1,
                           const float* __restrict__ Wk2, const float* __restrict__ Wv2,
                           const float* __restrict__ Wk3, const float* __restrict__ Wv3)
{
    int i = blockIdx.x * 256 + threadIdx.x;
    if (i < 4096) { wsplit_one(Wk1, g_w1k_h, g_w1k_l, 32, 128, i); return; }
    i -= 4096;
    if (i < 4096) { wsplit_one(Wv1, g_w1v_h, g_w1v_l, 32, 128, i); return; }
    i -= 4096;
    if (i < 16384) { wsplit_one(Wk2, g_w2k_h, g_w2k_l, 128, 128, i); return; }
    i -= 16384;
    if (i < 16384) { wsplit_one(Wv2, g_w2v_h, g_w2v_l, 128, 128, i); return; }
    i -= 16384;
    if (i < 65536) { wsplit_one(Wk3, g_w3k_h, g_w3k_l, 128, 512, i); return; }
    i -= 65536;
    if (i < 131072) { wsplit_one(Wv3, g_w3v_h, g_w3v_l, 128, 1024, i); }
}

// ---------------- full MLP chain + contraction (device body), 256 threads ----------------
// NOUT=16/NB=8: V path;  NOUT=8/NB=4: K path (logits)
template <int NOUT, int NB>
__device__ __forceinline__ void chain_body(
    char* sm,
    const float* __restrict__ edge_data,
    const __nv_bfloat16* __restrict__ W1h, const __nv_bfloat16* __restrict__ W1l,
    const float* __restrict__ b1,
    const __nv_bfloat16* __restrict__ W2h, const __nv_bfloat16* __restrict__ W2l,
    const float* __restrict__ b2,
    const __nv_bfloat16* __restrict__ W3h, const __nv_bfloat16* __restrict__ W3l,
    const float* __restrict__ b3,
    const int* __restrict__ ei, const float* __restrict__ sh)
{
    constexpr int P = 136, PA = 40;
    constexpr int NTOT = NB * 128;
    constexpr int NSLOT = (NOUT == 16) ? 4 : 2;
    constexpr int PP = NOUT + 1;
    __nv_bfloat16* H1h = (__nv_bfloat16*)(sm);
    __nv_bfloat16* H1l = (__nv_bfloat16*)(sm + 34816);
    __nv_bfloat16* WBh = (__nv_bfloat16*)(sm + 69632);
    __nv_bfloat16* WBl = (__nv_bfloat16*)(sm + 104448);
    __nv_bfloat16* H2h = (__nv_bfloat16*)(sm + 139264);
    __nv_bfloat16* H2l = (__nv_bfloat16*)(sm + 174080);
    __nv_bfloat16* EAh = (__nv_bfloat16*)(sm + 139264);           // phase-1 scratch
    __nv_bfloat16* EAl = (__nv_bfloat16*)(sm + 149504);
    __nv_bfloat16* W1sh = (__nv_bfloat16*)(sm + 159744);
    __nv_bfloat16* W1sl = (__nv_bfloat16*)(sm + 169984);
    float* u_s = (float*)sm;
    float* part = (float*)(sm + 33280);
    float* bs = (float*)(sm + 208896);

    const int tid = threadIdx.x, lane = tid & 31, warp = tid >> 5;
    const int m0 = blockIdx.x * 128;
    const int wm = (warp >> 2) * 64, wn = (warp & 3) * 32;

    float c[4][4][4];
    uint4 ph[8], pl[8];

    // ===== phase 1: h1 = relu(edge @ W1^T + b1) =====
    for (int i = tid; i < 128 * 8; i += 256) {
        int row = i >> 3, c4 = (i & 7) * 4;
        float4 v = *(const float4*)(edge_data + (size_t)(m0 + row) * 32 + c4);
        __nv_bfloat16 h[4], l[4];
        split2(v.x, h[0], l[0]); split2(v.y, h[1], l[1]);
        split2(v.z, h[2], l[2]); split2(v.w, h[3], l[3]);
        *(uint2*)&EAh[row * PA + c4] = *(uint2*)h;
        *(uint2*)&EAl[row * PA + c4] = *(uint2*)l;
    }
    for (int i = tid; i < 128 * 4; i += 256) {
        int row = i >> 2, c8 = (i & 3) * 8;
        *(uint4*)&W1sh[row * PA + c8] = ((const uint4*)W1h)[i];
        *(uint4*)&W1sl[row * PA + c8] = ((const uint4*)W1l)[i];
    }
    ldg_blk(W2h, W2l, tid, ph, pl);     // prefetch W2 under phase-1 mma
    __syncthreads();

    #pragma unroll
    for (int mt = 0; mt < 4; mt++)
        #pragma unroll
        for (int nt = 0; nt < 4; nt++)
            #pragma unroll
            for (int j = 0; j < 4; j++) c[mt][nt][j] = 0.f;
    mma_block<2, PA>(smem_u32(EAh), smem_u32(EAl), smem_u32(W1sh), smem_u32(W1sl),
                     lane, wm, wn, c);
    epi_split_store(c, b1, H1h, H1l, lane, wm, wn);

    // ===== phase 2: h2 = relu(h1 @ W2^T + b2) =====
    sts_blk(WBh, WBl, tid, ph, pl);     // W2 -> smem
    ldg_blk(W3h, W3l, tid, ph, pl);     // prefetch W3 block 0 under phase-2 mma
    __syncthreads();                    // h1 + W2 visible; phase-1 scratch reads done

    #pragma unroll
    for (int mt = 0; mt < 4; mt++)
        #pragma unroll
        for (int nt = 0; nt < 4; nt++)
            #pragma unroll
            for (int j = 0; j < 4; j++) c[mt][nt][j] = 0.f;
    mma_block<8, P>(smem_u32(H1h), smem_u32(H1l), smem_u32(WBh), smem_u32(WBl),
                    lane, wm, wn, c);
    epi_split_store(c, b2, H2h, H2l, lane, wm, wn);
    __syncthreads();   // all warps done reading h1/WB; h2 written

    // ===== phase 3: layer-3 GEMM streamed over n-blocks, fused contraction =====
    for (int i = tid; i < 128 * 64; i += 256) {
        int row = i >> 6, as = i & 63;
        int e = m0 + row;
        int src = ei[e];
        u_s[row * 65 + as] = g_t[src * 16 + (as >> 2)] * sh[e * 4 + (as & 3)] * 0.125f;
    }
    for (int i = tid; i < NTOT; i += 256) bs[i] = b3[i];
    sts_blk(WBh, WBl, tid, ph, pl);     // W3 block 0 -> smem
    __syncthreads();

    float loc[8][NSLOT];
    #pragma unroll
    for (int s = 0; s < 8; s++)
        #pragma unroll
        for (int j = 0; j < NSLOT; j++) loc[s][j] = 0.f;

    const uint32_t sH2h = smem_u32(H2h), sH2l = smem_u32(H2l);
    const uint32_t sWBh = smem_u32(WBh), sWBl = smem_u32(WBl);

    for (int nb = 0; nb < NB; nb++) {
        if (nb + 1 < NB)                 // prefetch next block under this mma
            ldg_blk(W3h + (size_t)(nb + 1) * 128 * 128,
                    W3l + (size_t)(nb + 1) * 128 * 128, tid, ph, pl);

        #pragma unroll
        for (int mt = 0; mt < 4; mt++)
            #pragma unroll
            for (int nt = 0; nt < 4; nt++)
                #pragma unroll
                for (int j = 0; j < 4; j++) c[mt][nt][j] = 0.f;
        mma_block<8, P>(sH2h, sH2l, sWBh, sWBl, lane, wm, wn, c);

        #pragma unroll
        for (int mt = 0; mt < 4; mt++) {
            int r = wm + mt * 16 + (lane >> 2);
            #pragma unroll
            for (int nt = 0; nt < 4; nt++) {
                int colb = nb * 128 + wn + nt * 8;
                int as = (NOUT == 16) ? (colb >> 4) : (colb >> 3);
                int obi = (NOUT == 16) ? ((nt & 1) * 2) : 0;
                float ur = u_s[r * 65 + as];
                float ur8 = u_s[(r + 8) * 65 + as];
                loc[mt * 2][obi]         += c[mt][nt][0] * ur;
                loc[mt * 2][obi + 1]     += c[mt][nt][1] * ur;
                loc[mt * 2 + 1][obi]     += c[mt][nt][2] * ur8;
                loc[mt * 2 + 1][obi + 1] += c[mt][nt][3] * ur8;
            }
        }

        if (nb + 1 < NB) {
            __syncthreads();             // mma done reading WB
            sts_blk(WBh, WBl, tid, ph, pl);
            __syncthreads();             // next block visible
        }
    }

    // per-warp partials -> smem
    {
        int wi = warp & 3;
        #pragma unroll
        for (int s = 0; s < 8; s++) {
            int row = wm + (s >> 1) * 16 + (s & 1) * 8 + (lane >> 2);
            #pragma unroll
            for (int j = 0; j < NSLOT; j++) {
                int ob = (lane & 3) * 2 + (j & 1) + (j >> 1) * 8;
                part[(wi * 128 + row) * PP + ob] = loc[s][j];
            }
        }
    }
    __syncthreads();

    if (NOUT == 16) {
        for (int idx = tid; idx < 128 * 16; idx += 256) {
            int row = idx >> 4, ob = idx & 15;
            float s = part[row * PP + ob] + part[(128 + row) * PP + ob]
                    + part[(256 + row) * PP + ob] + part[(384 + row) * PP + ob];
            float bt = 0.f;
            #pragma unroll
            for (int as = 0; as < 64; as++) bt = fmaf(u_s[row * 65 + as], bs[as * 16 + ob], bt);
            g_vbuf[(size_t)(m0 + row) * 16 + ob] = s + bt;
        }
    } else {
        for (int idx = tid; idx < 128 * 8; idx += 256) {
            int row = idx >> 3, b = idx & 7;
            float s = part[row * PP + b] + part[(128 + row) * PP + b]
                    + part[(256 + row) * PP + b] + part[(384 + row) * PP + b];
            float bt = 0.f;
            #pragma unroll
            for (int as = 0; as < 64; as++) bt = fmaf(u_s[row * 65 + as], bs[as * 8 + b], bt);
            part[row * PP + b] = s + bt;
        }
        __syncthreads();
        if (tid < 128) {
            int e = m0 + tid;
            int dst = ei[NE + e];
            float lp = 0.f;
            #pragma unroll
            for (int b = 0; b < 8; b++) lp += part[tid * PP + b] * g_qW[dst * 8 + b];
            g_logit[e] = lp;
            atomicMaxF(&g_m[dst], lp);
        }
    }
}

// one kernel runs the V chain then the K chain on the same 128 edges
__global__ __launch_bounds__(256, 1) void chain_both(
    const float* __restrict__ edge_data,
    const __nv_bfloat16* __restrict__ Wv1h, const __nv_bfloat16* __restrict__ Wv1l,
    const float* __restrict__ bv1,
    const __nv_bfloat16* __restrict__ Wv2h, const __nv_bfloat16* __restrict__ Wv2l,
    const float* __restrict__ bv2,
    const __nv_bfloat16* __restrict__ Wv3h, const __nv_bfloat16* __restrict__ Wv3l,
    const float* __restrict__ bv3,
    const __nv_bfloat16* __restrict__ Wk1h, const __nv_bfloat16* __restrict__ Wk1l,
    const float* __restrict__ bk1,
    const __nv_bfloat16* __restrict__ Wk2h, const __nv_bfloat16* __restrict__ Wk2l,
    const float* __restrict__ bk2,
    const __nv_bfloat16* __restrict__ Wk3h, const __nv_bfloat16* __restrict__ Wk3l,
    const float* __restrict__ bk3,
    const int* __restrict__ ei, const float* __restrict__ sh)
{
    extern __shared__ char sm[];
    chain_body<16, 8>(sm, edge_data, Wv1h, Wv1l, bv1, Wv2h, Wv2l, bv2,
                      Wv3h, Wv3l, bv3, ei, sh);
    __syncthreads();
    chain_body<8, 4>(sm, edge_data, Wk1h, Wk1l, bk1, Wk2h, Wk2l, bk2,
                     Wk3h, Wk3l, bk3, ei, sh);
}

// ---------------- init ----------------
__global__ void init_kernel() {
    int i = blockIdx.x * 256 + threadIdx.x;
    if (i < NN) { g_m[i] = -INFINITY; g_z[i] = 0.f; }
    if (i < NN * 16) g_agg[i] = 0.f;
    if (i < 64) { g_colsum[i] = 0.f; g_colsumsq[i] = 0.f; }
}

// ---------------- node linears ----------------
__global__ __launch_bounds__(128) void node_kernel(
    const float* __restrict__ node_data, const float* __restrict__ W_input,
    const float* __restrict__ W_query, const float* __restrict__ W_dot)
{
    __shared__ float Wi[64 * 16];
    __shared__ float Wq[16 * 8];
    __shared__ float Wd[64];
    __shared__ float tsh[8][16];
    __shared__ float qsh[8][8];
    int tid = threadIdx.x;
    for (int i = tid; i < 1024; i += 128) Wi[i] = W_input[i];
    if (tid < 128) Wq[tid] = W_query[tid];
    if (tid < 64) Wd[tid] = W_dot[tid];
    __syncthreads();

    int n_loc = tid >> 4, c = tid & 15;
    int n = blockIdx.x * 8 + n_loc;
    float tv = 0.f;
    if (n < NN) {
        const float* nd = node_data + (size_t)n * 64;
        #pragma unroll 8
        for (int i = 0; i < 64; i++) tv += nd[i] * Wi[i * 16 + c];
        tv *= 0.125f;
        g_t[n * 16 + c] = tv;
    }
    tsh[n_loc][c] = tv;
    __syncthreads();

    if (tid < 64) {
        int nl = tid >> 3, b = tid & 7;
        float qv = 0.f;
        #pragma unroll
        for (int a = 0; a < 16; a++) qv += tsh[nl][a] * Wq[a * 8 + b];
        qsh[nl][b] = qv * 0.25f;
    }
    __syncthreads();
    if (tid < 64) {
        int nl = tid >> 3, b = tid & 7;
        int n2 = blockIdx.x * 8 + nl;
        if (n2 < NN) {
            float s = 0.f;
            #pragma unroll
            for (int a = 0; a < 8; a++) s += qsh[nl][a] * Wd[a * 8 + b];
            g_qW[n2 * 8 + b] = s * 0.125f;
        }
    }
}

// ---------------- softmax numerator + segment sums ----------------
__global__ void attn_agg_kernel(const int* __restrict__ ei)
{
    int e = blockIdx.x * 256 + threadIdx.x;
    if (e >= NE) return;
    int dst = ei[NE + e];
    float p = expf(g_logit[e] - g_m[dst]);
    atomicAdd(&g_z[dst], p);
    const float* v = g_vbuf + (size_t)e * 16;
    float* agg = g_agg + dst * 16;
    #pragma unroll
    for (int c = 0; c < 16; c++) atomicAdd(&agg[c], p * v[c]);
}

// ---------------- output linear + residual + BN stats ----------------
__global__ __launch_bounds__(256) void out_stats_kernel(
    const float* __restrict__ node_data, const float* __restrict__ W_output)
{
    __shared__ float Wsh[16 * 64];
    __shared__ float red[256];
    int tid = threadIdx.x;
    for (int i = tid; i < 1024; i += 256) Wsh[i] = W_output[i];
    __syncthreads();

    int c = tid & 63;
    int r = tid >> 6;
    int n0 = blockIdx.x * 64;
    float lsum = 0.f, lsq = 0.f;
    for (int i = 0; i < 16; i++) {
        int n = n0 + r + i * 4;
        if (n < NN) {
            float zz = g_z[n];
            float inv = zz > 0.f ? 0.25f / zz : 0.f;
            float o = 0.f;
            const float* agg = g_agg + n * 16;
            #pragma unroll
            for (int j = 0; j < 16; j++) o += agg[j] * Wsh[j * 64 + c];
            o = o * inv + node_data[(size_t)n * 64 + c];
            g_outpre[(size_t)n * 64 + c] = o;
            lsum += o;
            lsq += o * o;
        }
    }
    red[tid] = lsum;
    __syncthreads();
    if (r == 0) atomicAdd(&g_colsum[c], red[c] + red[64 + c] + red[128 + c] + red[192 + c]);
    __syncthreads();
    red[tid] = lsq;
    __syncthreads();
    if (r == 0) atomicAdd(&g_colsumsq[c], red[c] + red[64 + c] + red[128 + c] + red[192 + c]);
}

// ---------------- batchnorm finalize ----------------
__global__ void bn_kernel(const float* __restrict__ bnw, const float* __restrict__ bnb,
                          float* __restrict__ out)
{
    int i = blockIdx.x * 256 + threadIdx.x;
    if (i >= NN * 64) return;
    int c = i & 63;
    const float invN = 1.f / NN;
    float mean = g_colsum[c] * invN;
    float var = g_colsumsq[c] * invN - mean * mean;
    out[i] = (g_outpre[i] - mean) * rsqrtf(var + 1e-5f) * bnw[c] + bnb[c];
}

// ---------------- launch ----------------
extern "C" void kernel_launch(void* const* d_in, const int* in_sizes, int n_in,
                              void* d_out, int out_size)
{
    const float* node_data = (const float*)d_in[0];
    const int*   edge_index = (const int*)d_in[1];
    const float* edge_data = (const float*)d_in[2];
    const float* edge_sh   = (const float*)d_in[3];
    const float* W_input = (const float*)d_in[4];
    const float* W_query = (const float*)d_in[5];
    const float* W_dot   = (const float*)d_in[6];
    const float* W_output = (const float*)d_in[7];
    const float* Wk1 = (const float*)d_in[8];
    const float* bk1 = (const float*)d_in[9];
    const float* Wk2 = (const float*)d_in[10];
    const float* bk2 = (const float*)d_in[11];
    const float* Wk3 = (const float*)d_in[12];
    const float* bk3 = (const float*)d_in[13];
    const float* Wv1 = (const float*)d_in[14];
    const float* bv1 = (const float*)d_in[15];
    const float* Wv2 = (const float*)d_in[16];
    const float* bv2 = (const float*)d_in[17];
    const float* Wv3 = (const float*)d_in[18];
    const float* bv3 = (const float*)d_in[19];
    const float* bn_weight = (const float*)d_in[20];
    const float* bn_bias   = (const float*)d_in[21];
    float* out = (float*)d_out;

    void *pw1kh, *pw1kl, *pw1vh, *pw1vl, *pw2kh, *pw2kl, *pw2vh, *pw2vl;
    void *pw3kh, *pw3kl, *pw3vh, *pw3vl;
    cudaGetSymbolAddress(&pw1kh, g_w1k_h); cudaGetSymbolAddress(&pw1kl, g_w1k_l);
    cudaGetSymbolAddress(&pw1vh, g_w1v_h); cudaGetSymbolAddress(&pw1vl, g_w1v_l);
    cudaGetSymbolAddress(&pw2kh, g_w2k_h); cudaGetSymbolAddress(&pw2kl, g_w2k_l);
    cudaGetSymbolAddress(&pw2vh, g_w2v_h); cudaGetSymbolAddress(&pw2vl, g_w2v_l);
    cudaGetSymbolAddress(&pw3kh, g_w3k_h); cudaGetSymbolAddress(&pw3kl, g_w3k_l);
    cudaGetSymbolAddress(&pw3vh, g_w3v_h); cudaGetSymbolAddress(&pw3vl, g_w3v_l);

    const int SMC = 208896 + 4096;   // 212992
    cudaFuncSetAttribute(chain_both, cudaFuncAttributeMaxDynamicSharedMemorySize, SMC);

    init_kernel<<<(NE + 255) / 256, 256>>>();                                   // 0
    wsplit_all<<<(237568 + 255) / 256, 256>>>(Wk1, Wv1, Wk2, Wv2, Wk3, Wv3);    // 1
    node_kernel<<<(NN + 7) / 8, 128>>>(node_data, W_input, W_query, W_dot);     // 2
    chain_both<<<NE / 128, 256, SMC>>>(                                         // 3
        edge_data,
        (const __nv_bfloat16*)pw1vh, (const __nv_bfloat16*)pw1vl, bv1,
        (const __nv_bfloat16*)pw2vh, (const __nv_bfloat16*)pw2vl, bv2,
        (const __nv_bfloat16*)pw3vh, (const __nv_bfloat16*)pw3vl, bv3,
        (const __nv_bfloat16*)pw1kh, (const __nv_bfloat16*)pw1kl, bk1,
        (const __nv_bfloat16*)pw2kh, (const __nv_bfloat16*)pw2kl, bk2,
        (const __nv_bfloat16*)pw3kh, (const __nv_bfloat16*)pw3kl, bk3,
        edge_index, edge_sh);

    attn_agg_kernel<<<(NE + 255) / 256, 256>>>(edge_index);                     // 4
    out_stats_kernel<<<(NN + 63) / 64, 256>>>(node_data, W_output);             // 5
    bn_kernel<<<(NN * 64 + 255) / 256, 256>>>(bn_weight, bn_bias, out);         // 6
}

// round 12
// speedup vs baseline: 1.0979x; 1.0034x over previous
#include <cuda_runtime.h>
#include <cuda_bf16.h>
#include <stdint.h>
#include <math.h>

#define NN 10000
#define NE 160000

// ---------------- device scratch (static, allocation-free) ----------------
__device__ float g_t[NN * 16];
__device__ float g_qW[NN * 8];
// transposed, split weights [N, K] bf16
__device__ __align__(16) __nv_bfloat16 g_w1k_h[128 * 32], g_w1k_l[128 * 32];
__device__ __align__(16) __nv_bfloat16 g_w1v_h[128 * 32], g_w1v_l[128 * 32];
__device__ __align__(16) __nv_bfloat16 g_w2k_h[128 * 128], g_w2k_l[128 * 128];
__device__ __align__(16) __nv_bfloat16 g_w2v_h[128 * 128], g_w2v_l[128 * 128];
__device__ __align__(16) __nv_bfloat16 g_w3k_h[512 * 128], g_w3k_l[512 * 128];
__device__ __align__(16) __nv_bfloat16 g_w3v_h[1024 * 128], g_w3v_l[1024 * 128];
// fp32 tail
__device__ float g_vbuf[(size_t)NE * 16];
__device__ float g_logit[NE];
__device__ float g_m[NN];
__device__ float g_z[NN];
__device__ float g_agg[NN * 16];
__device__ float g_colsum[64];
__device__ float g_colsumsq[64];
__device__ float g_outpre[NN * 64];

// ---------------- helpers ----------------
__device__ __forceinline__ void atomicMaxF(float* addr, float v) {
    if (v >= 0.f)
        atomicMax((int*)addr, __float_as_int(v));
    else
        atomicMin((unsigned int*)addr, __float_as_uint(v));
}

__device__ __forceinline__ uint32_t smem_u32(const void* p) {
    uint32_t a;
    asm("{ .reg .u64 t; cvta.to.shared.u64 t, %1; cvt.u32.u64 %0, t; }" : "=r"(a) : "l"(p));
    return a;
}

__device__ __forceinline__ void split2(float x, __nv_bfloat16& h, __nv_bfloat16& l) {
    h = __float2bfloat16(x);
    l = __float2bfloat16(x - __bfloat162float(h));
}

__device__ __forceinline__ void ldm4(uint32_t* r, uint32_t addr) {
    asm volatile("ldmatrix.sync.aligned.m8n8.x4.shared.b16 {%0,%1,%2,%3}, [%4];"
                 : "=r"(r[0]), "=r"(r[1]), "=r"(r[2]), "=r"(r[3]) : "r"(addr));
}

__device__ __forceinline__ void mma16816(float* c, const uint32_t* a, const uint32_t* b) {
    asm volatile(
        "mma.sync.aligned.m16n8k16.row.col.f32.bf16.bf16.f32 "
        "{%0,%1,%2,%3}, {%4,%5,%6,%7}, {%8,%9}, {%0,%1,%2,%3};"
        : "+f"(c[0]), "+f"(c[1]), "+f"(c[2]), "+f"(c[3])
        : "r"(a[0]), "r"(a[1]), "r"(a[2]), "r"(a[3]), "r"(b[0]), "r"(b[1]));
}

#define CPA16(smaddr, gptr) \
    asm volatile("cp.async.ca.shared.global [%0], [%1], 16;" :: "r"(smaddr), "l"(gptr) : "memory")
#define CPA_COMMIT asm volatile("cp.async.commit_group;" ::: "memory")
#define CPA_WAIT0 asm volatile("cp.async.wait_group 0;" ::: "memory")

// async-copy one 64-row x 128-col bf16 hi/lo chunk into a [64][136] smem buffer
__device__ __forceinline__ void cpa_chunk(uint32_t bufh, uint32_t bufl,
                                          const __nv_bfloat16* gh, const __nv_bfloat16* gl,
                                          int tid) {
    #pragma unroll
    for (int r = 0; r < 4; r++) {
        int i = tid + r * 256;
        int row = i >> 4, c8 = (i & 15) * 8;
        uint32_t so = (uint32_t)(row * 136 + c8) * 2;
        CPA16(bufh + so, (const char*)gh + (size_t)i * 16);
        CPA16(bufl + so, (const char*)gl + (size_t)i * 16);
    }
}

// 3-term split MMA with hoisted fragments. MT m-tiles of 16, 32 n-cols.
template <int KS, int PITCH, int MT>
__device__ __forceinline__ void mma_block(
    uint32_t aH, uint32_t aL, uint32_t bH, uint32_t bL,
    int lane, int wm, int wn, float c[MT][4][4])
{
    #pragma unroll
    for (int kk = 0; kk < KS; kk++) {
        uint32_t ah[MT][4], al[MT][4], bh[2][4], bl[2][4];
        #pragma unroll
        for (int mt = 0; mt < MT; mt++) {
            int row = wm + mt * 16 + (lane & 15);
            uint32_t off = (uint32_t)(row * PITCH + kk * 16 + 8 * (lane >> 4)) << 1;
            ldm4(ah[mt], aH + off);
            ldm4(al[mt], aL + off);
        }
        #pragma unroll
        for (int np = 0; np < 2; np++) {
            int row = wn + np * 16 + ((lane >> 4) << 3) + (lane & 7);
            uint32_t off = (uint32_t)(row * PITCH + kk * 16 + 8 * ((lane >> 3) & 1)) << 1;
            ldm4(bh[np], bH + off);
            ldm4(bl[np], bL + off);
        }
        #pragma unroll
        for (int mt = 0; mt < MT; mt++)
            #pragma unroll
            for (int nt = 0; nt < 4; nt++) {
                uint32_t bbh[2] = { bh[nt >> 1][(nt & 1) * 2], bh[nt >> 1][(nt & 1) * 2 + 1] };
                uint32_t bbl[2] = { bl[nt >> 1][(nt & 1) * 2], bl[nt >> 1][(nt & 1) * 2 + 1] };
                mma16816(c[mt][nt], ah[mt], bbh);
                mma16816(c[mt][nt], ah[mt], bbl);
                mma16816(c[mt][nt], al[mt], bbh);
            }
    }
}

// bias + relu + split-store fragments into a [*][136] hi/lo smem tile at column base cb
template <int MT>
__device__ __forceinline__ void epi_split_store(
    float c[MT][4][4], const float* __restrict__ bias,
    __nv_bfloat16* Dh, __nv_bfloat16* Dl, int lane, int wm, int wn, int cb)
{
    constexpr int P = 136;
    #pragma unroll
    for (int mt = 0; mt < MT; mt++) {
        int r0 = wm + mt * 16 + (lane >> 2);
        #pragma unroll
        for (int nt = 0; nt < 4; nt++) {
            int col = cb + wn + nt * 8 + (lane & 3) * 2;
            float b0 = __ldg(bias + col), b1 = __ldg(bias + col + 1);
            float v0 = fmaxf(c[mt][nt][0] + b0, 0.f);
            float v1 = fmaxf(c[mt][nt][1] + b1, 0.f);
            float v2 = fmaxf(c[mt][nt][2] + b0, 0.f);
            float v3 = fmaxf(c[mt][nt][3] + b1, 0.f);
            __nv_bfloat16 h0, l0, h1, l1;
            split2(v0, h0, l0); split2(v1, h1, l1);
            *(__nv_bfloat162*)&Dh[r0 * P + col] = __nv_bfloat162(h0, h1);
            *(__nv_bfloat162*)&Dl[r0 * P + col] = __nv_bfloat162(l0, l1);
            split2(v2, h0, l0); split2(v3, h1, l1);
            *(__nv_bfloat162*)&Dh[(r0 + 8) * P + col] = __nv_bfloat162(h0, h1);
            *(__nv_bfloat162*)&Dl[(r0 + 8) * P + col] = __nv_bfloat162(l0, l1);
        }
    }
}

// ---------------- weight prep ----------------
__device__ __forceinline__ void wsplit_one(const float* src, __nv_bfloat16* dh,
                                           __nv_bfloat16* dl, int K, int N, int i) {
    int n = i / K, k = i % K;
    __nv_bfloat16 h, l;
    split2(src[k * N + n], h, l);
    dh[i] = h;
    dl[i] = l;
}

__global__ void wsplit_all(const float* __restrict__ Wk1, const float* __restrict__ Wv1,
                           const float* __restrict__ Wk2, const float* __restrict__ Wv2,
                           const float* __restrict__ Wk3, const float* __restrict__ Wv3)
{
    int i = blockIdx.x * 256 + threadIdx.x;
    if (i < 4096) { wsplit_one(Wk1, g_w1k_h, g_w1k_l, 32, 128, i); return; }
    i -= 4096;
    if (i < 4096) { wsplit_one(Wv1, g_w1v_h, g_w1v_l, 32, 128, i); return; }
    i -= 4096;
    if (i < 16384) { wsplit_one(Wk2, g_w2k_h, g_w2k_l, 128, 128, i); return; }
    i -= 16384;
    if (i < 16384) { wsplit_one(Wv2, g_w2v_h, g_w2v_l, 128, 128, i); return; }
    i -= 16384;
    if (i < 65536) { wsplit_one(Wk3, g_w3k_h, g_w3k_l, 128, 512, i); return; }
    i -= 65536;
    if (i < 131072) { wsplit_one(Wv3, g_w3v_h, g_w3v_l, 128, 1024, i); }
}

// ---------------- full MLP chain + contraction (device body), 256 threads ----------------
// NOUT=16/NB=8: V path;  NOUT=8/NB=4: K path (logits)
template <int NOUT, int NB>
__device__ __forceinline__ void chain_body(
    char* sm,
    const float* __restrict__ edge_data,
    const __nv_bfloat16* __restrict__ W1h, const __nv_bfloat16* __restrict__ W1l,
    const float* __restrict__ b1,
    const __nv_bfloat16* __restrict__ W2h, const __nv_bfloat16* __restrict__ W2l,
    const float* __restrict__ b2,
    const __nv_bfloat16* __restrict__ W3h, const __nv_bfloat16* __restrict__ W3l,
    const float* __restrict__ b3,
    const int* __restrict__ ei, const float* __restrict__ sh)
{
    constexpr int P = 136, PA = 40;
    constexpr int NTOT = NB * 128;
    constexpr int NC = NB * 2;                  // 64-col chunks
    constexpr int NSLOT = (NOUT == 16) ? 4 : 2;
    constexpr int PP = NOUT + 1;
    __nv_bfloat16* H1h = (__nv_bfloat16*)(sm);
    __nv_bfloat16* H1l = (__nv_bfloat16*)(sm + 34816);
    // WB region: two 64-col double buffers (each h 17408 B + l 17408 B)
    __nv_bfloat16* B0h = (__nv_bfloat16*)(sm + 69632);
    __nv_bfloat16* B0l = (__nv_bfloat16*)(sm + 87040);
    __nv_bfloat16* B1h = (__nv_bfloat16*)(sm + 104448);
    __nv_bfloat16* B1l = (__nv_bfloat16*)(sm + 121856);
    __nv_bfloat16* H2h = (__nv_bfloat16*)(sm + 139264);
    __nv_bfloat16* H2l = (__nv_bfloat16*)(sm + 174080);
    __nv_bfloat16* EAh = (__nv_bfloat16*)(sm + 139264);           // phase-1 scratch
    __nv_bfloat16* EAl = (__nv_bfloat16*)(sm + 149504);
    __nv_bfloat16* W1sh = (__nv_bfloat16*)(sm + 159744);
    __nv_bfloat16* W1sl = (__nv_bfloat16*)(sm + 169984);
    float* u_s = (float*)sm;
    float* part = (float*)(sm + 33280);
    float* bs = (float*)(sm + 208896);

    const int tid = threadIdx.x, lane = tid & 31, warp = tid >> 5;
    const int m0 = blockIdx.x * 128;
    // phase-1 warp grid: 2(m) x 4(n), 64x32 tiles
    const int wm1 = (warp >> 2) * 64, wn1 = (warp & 3) * 32;
    // phase-2/3 warp grid: 4(m) x 2(n), 32x32 tiles
    const int wm2 = (warp >> 1) * 32, wn2 = (warp & 1) * 32;

    const uint32_t sB0h = smem_u32(B0h), sB0l = smem_u32(B0l);
    const uint32_t sB1h = smem_u32(B1h), sB1l = smem_u32(B1l);

    // ===== phase 1: h1 = relu(edge @ W1^T + b1) =====
    for (int i = tid; i < 128 * 8; i += 256) {
        int row = i >> 3, c4 = (i & 7) * 4;
        float4 v = *(const float4*)(edge_data + (size_t)(m0 + row) * 32 + c4);
        __nv_bfloat16 h[4], l[4];
        split2(v.x, h[0], l[0]); split2(v.y, h[1], l[1]);
        split2(v.z, h[2], l[2]); split2(v.w, h[3], l[3]);
        *(uint2*)&EAh[row * PA + c4] = *(uint2*)h;
        *(uint2*)&EAl[row * PA + c4] = *(uint2*)l;
    }
    for (int i = tid; i < 128 * 4; i += 256) {
        int row = i >> 2, c8 = (i & 3) * 8;
        *(uint4*)&W1sh[row * PA + c8] = ((const uint4*)W1h)[i];
        *(uint4*)&W1sl[row * PA + c8] = ((const uint4*)W1l)[i];
    }
    // async prefetch W2 (both 64-col chunks) into the double buffers
    cpa_chunk(sB0h, sB0l, W2h, W2l, tid);
    cpa_chunk(sB1h, sB1l, W2h + 64 * 128, W2l + 64 * 128, tid);
    CPA_COMMIT;
    __syncthreads();

    {
        float c1[4][4][4];
        #pragma unroll
        for (int mt = 0; mt < 4; mt++)
            #pragma unroll
            for (int nt = 0; nt < 4; nt++)
                #pragma unroll
                for (int j = 0; j < 4; j++) c1[mt][nt][j] = 0.f;
        mma_block<2, PA, 4>(smem_u32(EAh), smem_u32(EAl), smem_u32(W1sh), smem_u32(W1sl),
                            lane, wm1, wn1, c1);
        epi_split_store<4>(c1, b1, H1h, H1l, lane, wm1, wn1, 0);
    }
    CPA_WAIT0;
    __syncthreads();   // h1 + W2 chunks visible; phase-1 scratch reads done

    // ===== phase 2: h2 = relu(h1 @ W2^T + b2), two 64-col chunks =====
    #pragma unroll
    for (int ch = 0; ch < 2; ch++) {
        float c[2][4][4];
        #pragma unroll
        for (int mt = 0; mt < 2; mt++)
            #pragma unroll
            for (int nt = 0; nt < 4; nt++)
                #pragma unroll
                for (int j = 0; j < 4; j++) c[mt][nt][j] = 0.f;
        mma_block<8, P, 2>(smem_u32(H1h), smem_u32(H1l),
                           ch ? sB1h : sB0h, ch ? sB1l : sB0l,
                           lane, wm2, wn2, c);
        epi_split_store<2>(c, b2, H2h, H2l, lane, wm2, wn2, ch * 64);
    }
    __syncthreads();   // all warps done with H1/WB; h2 written

    // ===== phase 3: layer-3 GEMM streamed in 64-col chunks, fused contraction =====
    for (int i = tid; i < 128 * 64; i += 256) {
        int row = i >> 6, as = i & 63;
        int e = m0 + row;
        int src = ei[e];
        u_s[row * 65 + as] = g_t[src * 16 + (as >> 2)] * sh[e * 4 + (as & 3)] * 0.125f;
    }
    for (int i = tid; i < NTOT; i += 256) bs[i] = b3[i];
    cpa_chunk(sB0h, sB0l, W3h, W3l, tid);     // chunk 0
    CPA_COMMIT;

    float loc[4][NSLOT];
    #pragma unroll
    for (int s = 0; s < 4; s++)
        #pragma unroll
        for (int j = 0; j < NSLOT; j++) loc[s][j] = 0.f;

    const uint32_t sH2h = smem_u32(H2h), sH2l = smem_u32(H2l);

    for (int ch = 0; ch < NC; ch++) {
        CPA_WAIT0;
        __syncthreads();   // chunk ch visible; all warps done reading the other buffer
        if (ch + 1 < NC) {
            cpa_chunk((ch & 1) ? sB0h : sB1h, (ch & 1) ? sB0l : sB1l,
                      W3h + (size_t)(ch + 1) * 64 * 128,
                      W3l + (size_t)(ch + 1) * 64 * 128, tid);
            CPA_COMMIT;
        }

        float c[2][4][4];
        #pragma unroll
        for (int mt = 0; mt < 2; mt++)
            #pragma unroll
            for (int nt = 0; nt < 4; nt++)
                #pragma unroll
                for (int j = 0; j < 4; j++) c[mt][nt][j] = 0.f;
        mma_block<8, P, 2>(sH2h, sH2l,
                           (ch & 1) ? sB1h : sB0h, (ch & 1) ? sB1l : sB0l,
                           lane, wm2, wn2, c);

        #pragma unroll
        for (int mt = 0; mt < 2; mt++) {
            int r = wm2 + mt * 16 + (lane >> 2);
            #pragma unroll
            for (int nt = 0; nt < 4; nt++) {
                int colb = ch * 64 + wn2 + nt * 8;
                int as = (NOUT == 16) ? (colb >> 4) : (colb >> 3);
                int obi = (NOUT == 16) ? ((nt & 1) * 2) : 0;
                float ur = u_s[r * 65 + as];
                float ur8 = u_s[(r + 8) * 65 + as];
                loc[mt * 2][obi]         += c[mt][nt][0] * ur;
                loc[mt * 2][obi + 1]     += c[mt][nt][1] * ur;
                loc[mt * 2 + 1][obi]     += c[mt][nt][2] * ur8;
                loc[mt * 2 + 1][obi + 1] += c[mt][nt][3] * ur8;
            }
        }
    }

    // per-warp partials -> smem (2 n-warps per row)
    {
        int wi = warp & 1;
        #pragma unroll
        for (int s = 0; s < 4; s++) {
            int row = wm2 + (s >> 1) * 16 + (s & 1) * 8 + (lane >> 2);
            #pragma unroll
            for (int j = 0; j < NSLOT; j++) {
                int ob = (lane & 3) * 2 + (j & 1) + (j >> 1) * 8;
                part[(wi * 128 + row) * PP + ob] = loc[s][j];
            }
        }
    }
    __syncthreads();

    if (NOUT == 16) {
        for (int idx = tid; idx < 128 * 16; idx += 256) {
            int row = idx >> 4, ob = idx & 15;
            float s = part[row * PP + ob] + part[(128 + row) * PP + ob];
            float bt = 0.f;
            #pragma unroll
            for (int as = 0; as < 64; as++) bt = fmaf(u_s[row * 65 + as], bs[as * 16 + ob], bt);
            g_vbuf[(size_t)(m0 + row) * 16 + ob] = s + bt;
        }
    } else {
        for (int idx = tid; idx < 128 * 8; idx += 256) {
            int row = idx >> 3, b = idx & 7;
            float s = part[row * PP + b] + part[(128 + row) * PP + b];
            float bt = 0.f;
            #pragma unroll
            for (int as = 0; as < 64; as++) bt = fmaf(u_s[row * 65 + as], bs[as * 8 + b], bt);
            part[row * PP + b] = s + bt;
        }
        __syncthreads();
        if (tid < 128) {
            int e = m0 + tid;
            int dst = ei[NE + e];
            float lp = 0.f;
            #pragma unroll
            for (int b = 0; b < 8; b++) lp += part[tid * PP + b] * g_qW[dst * 8 + b];
            g_logit[e] = lp;
            atomicMaxF(&g_m[dst], lp);
        }
    }
}

// one kernel runs the V chain then the K chain on the same 128 edges
__global__ __launch_bounds__(256, 1) void chain_both(
    const float* __restrict__ edge_data,
    const __nv_bfloat16* __restrict__ Wv1h, const __nv_bfloat16* __restrict__ Wv1l,
    const float* __restrict__ bv1,
    const __nv_bfloat16* __restrict__ Wv2h, const __nv_bfloat16* __restrict__ Wv2l,
    const float* __restrict__ bv2,
    const __nv_bfloat16* __restrict__ Wv3h, const __nv_bfloat16* __restrict__ Wv3l,
    const float* __restrict__ bv3,
    const __nv_bfloat16* __restrict__ Wk1h, const __nv_bfloat16* __restrict__ Wk1l,
    const float* __restrict__ bk1,
    const __nv_bfloat16* __restrict__ Wk2h, const __nv_bfloat16* __restrict__ Wk2l,
    const float* __restrict__ bk2,
    const __nv_bfloat16* __restrict__ Wk3h, const __nv_bfloat16* __restrict__ Wk3l,
    const float* __restrict__ bk3,
    const int* __restrict__ ei, const float* __restrict__ sh)
{
    extern __shared__ char sm[];
    chain_body<16, 8>(sm, edge_data, Wv1h, Wv1l, bv1, Wv2h, Wv2l, bv2,
                      Wv3h, Wv3l, bv3, ei, sh);
    __syncthreads();
    chain_body<8, 4>(sm, edge_data, Wk1h, Wk1l, bk1, Wk2h, Wk2l, bk2,
                     Wk3h, Wk3l, bk3, ei, sh);
}

// ---------------- init ----------------
__global__ void init_kernel() {
    int i = blockIdx.x * 256 + threadIdx.x;
    if (i < NN) { g_m[i] = -INFINITY; g_z[i] = 0.f; }
    if (i < NN * 16) g_agg[i] = 0.f;
    if (i < 64) { g_colsum[i] = 0.f; g_colsumsq[i] = 0.f; }
}

// ---------------- node linears ----------------
__global__ __launch_bounds__(128) void node_kernel(
    const float* __restrict__ node_data, const float* __restrict__ W_input,
    const float* __restrict__ W_query, const float* __restrict__ W_dot)
{
    __shared__ float Wi[64 * 16];
    __shared__ float Wq[16 * 8];
    __shared__ float Wd[64];
    __shared__ float tsh[8][16];
    __shared__ float qsh[8][8];
    int tid = threadIdx.x;
    for (int i = tid; i < 1024; i += 128) Wi[i] = W_input[i];
    if (tid < 128) Wq[tid] = W_query[tid];
    if (tid < 64) Wd[tid] = W_dot[tid];
    __syncthreads();

    int n_loc = tid >> 4, c = tid & 15;
    int n = blockIdx.x * 8 + n_loc;
    float tv = 0.f;
    if (n < NN) {
        const float* nd = node_data + (size_t)n * 64;
        #pragma unroll 8
        for (int i = 0; i < 64; i++) tv += nd[i] * Wi[i * 16 + c];
        tv *= 0.125f;
        g_t[n * 16 + c] = tv;
    }
    tsh[n_loc][c] = tv;
    __syncthreads();

    if (tid < 64) {
        int nl = tid >> 3, b = tid & 7;
        float qv = 0.f;
        #pragma unroll
        for (int a = 0; a < 16; a++) qv += tsh[nl][a] * Wq[a * 8 + b];
        qsh[nl][b] = qv * 0.25f;
    }
    __syncthreads();
    if (tid < 64) {
        int nl = tid >> 3, b = tid & 7;
        int n2 = blockIdx.x * 8 + nl;
        if (n2 < NN) {
            float s = 0.f;
            #pragma unroll
            for (int a = 0; a < 8; a++) s += qsh[nl][a] * Wd[a * 8 + b];
            g_qW[n2 * 8 + b] = s * 0.125f;
        }
    }
}

// ---------------- softmax numerator + segment sums ----------------
__global__ void attn_agg_kernel(const int* __restrict__ ei)
{
    int e = blockIdx.x * 256 + threadIdx.x;
    if (e >= NE) return;
    int dst = ei[NE + e];
    float p = expf(g_logit[e] - g_m[dst]);
    atomicAdd(&g_z[dst], p);
    const float* v = g_vbuf + (size_t)e * 16;
    float* agg = g_agg + dst * 16;
    #pragma unroll
    for (int c = 0; c < 16; c++) atomicAdd(&agg[c], p * v[c]);
}

// ---------------- output linear + residual + BN stats ----------------
__global__ __launch_bounds__(256) void out_stats_kernel(
    const float* __restrict__ node_data, const float* __restrict__ W_output)
{
    __shared__ float Wsh[16 * 64];
    __shared__ float red[256];
    int tid = threadIdx.x;
    for (int i = tid; i < 1024; i += 256) Wsh[i] = W_output[i];
    __syncthreads();

    int c = tid & 63;
    int r = tid >> 6;
    int n0 = blockIdx.x * 64;
    float lsum = 0.f, lsq = 0.f;
    for (int i = 0; i < 16; i++) {
        int n = n0 + r + i * 4;
        if (n < NN) {
            float zz = g_z[n];
            float inv = zz > 0.f ? 0.25f / zz : 0.f;
            float o = 0.f;
            const float* agg = g_agg + n * 16;
            #pragma unroll
            for (int j = 0; j < 16; j++) o += agg[j] * Wsh[j * 64 + c];
            o = o * inv + node_data[(size_t)n * 64 + c];
            g_outpre[(size_t)n * 64 + c] = o;
            lsum += o;
            lsq += o * o;
        }
    }
    red[tid] = lsum;
    __syncthreads();
    if (r == 0) atomicAdd(&g_colsum[c], red[c] + red[64 + c] + red[128 + c] + red[192 + c]);
    __syncthreads();
    red[tid] = lsq;
    __syncthreads();
    if (r == 0) atomicAdd(&g_colsumsq[c], red[c] + red[64 + c] + red[128 + c] + red[192 + c]);
}

// ---------------- batchnorm finalize ----------------
__global__ void bn_kernel(const float* __restrict__ bnw, const float* __restrict__ bnb,
                          float* __restrict__ out)
{
    int i = blockIdx.x * 256 + threadIdx.x;
    if (i >= NN * 64) return;
    int c = i & 63;
    const float invN = 1.f / NN;
    float mean = g_colsum[c] * invN;
    float var = g_colsumsq[c] * invN - mean * mean;
    out[i] = (g_outpre[i] - mean) * rsqrtf(var + 1e-5f) * bnw[c] + bnb[c];
}

// ---------------- launch ----------------
extern "C" void kernel_launch(void* const* d_in, const int* in_sizes, int n_in,
                              void* d_out, int out_size)
{
    const float* node_data = (const float*)d_in[0];
    const int*   edge_index = (const int*)d_in[1];
    const float* edge_data = (const float*)d_in[2];
    const float* edge_sh   = (const float*)d_in[3];
    const float* W_input = (const float*)d_in[4];
    const float* W_query = (const float*)d_in[5];
    const float* W_dot   = (const float*)d_in[6];
    const float* W_output = (const float*)d_in[7];
    const float* Wk1 = (const float*)d_in[8];
    const float* bk1 = (const float*)d_in[9];
    const float* Wk2 = (const float*)d_in[10];
    const float* bk2 = (const float*)d_in[11];
    const float* Wk3 = (const float*)d_in[12];
    const float* bk3 = (const float*)d_in[13];
    const float* Wv1 = (const float*)d_in[14];
    const float* bv1 = (const float*)d_in[15];
    const float* Wv2 = (const float*)d_in[16];
    const float* bv2 = (const float*)d_in[17];
    const float* Wv3 = (const float*)d_in[18];
    const float* bv3 = (const float*)d_in[19];
    const float* bn_weight = (const float*)d_in[20];
    const float* bn_bias   = (const float*)d_in[21];
    float* out = (float*)d_out;

    void *pw1kh, *pw1kl, *pw1vh, *pw1vl, *pw2kh, *pw2kl, *pw2vh, *pw2vl;
    void *pw3kh, *pw3kl, *pw3vh, *pw3vl;
    cudaGetSymbolAddress(&pw1kh, g_w1k_h); cudaGetSymbolAddress(&pw1kl, g_w1k_l);
    cudaGetSymbolAddress(&pw1vh, g_w1v_h); cudaGetSymbolAddress(&pw1vl, g_w1v_l);
    cudaGetSymbolAddress(&pw2kh, g_w2k_h); cudaGetSymbolAddress(&pw2kl, g_w2k_l);
    cudaGetSymbolAddress(&pw2vh, g_w2v_h); cudaGetSymbolAddress(&pw2vl, g_w2v_l);
    cudaGetSymbolAddress(&pw3kh, g_w3k_h); cudaGetSymbolAddress(&pw3kl, g_w3k_l);
    cudaGetSymbolAddress(&pw3vh, g_w3v_h); cudaGetSymbolAddress(&pw3vl, g_w3v_l);

    const int SMC = 208896 + 4096;   // 212992
    cudaFuncSetAttribute(chain_both, cudaFuncAttributeMaxDynamicSharedMemorySize, SMC);

    init_kernel<<<(NE + 255) / 256, 256>>>();                                   // 0
    wsplit_all<<<(237568 + 255) / 256, 256>>>(Wk1, Wv1, Wk2, Wv2, Wk3, Wv3);    // 1
    node_kernel<<<(NN + 7) / 8, 128>>>(node_data, W_input, W_query, W_dot);     // 2
    chain_both<<<NE / 128, 256, SMC>>>(                                         // 3
        edge_data,
        (const __nv_bfloat16*)pw1vh, (const __nv_bfloat16*)pw1vl, bv1,
        (const __nv_bfloat16*)pw2vh, (const __nv_bfloat16*)pw2vl, bv2,
        (const __nv_bfloat16*)pw3vh, (const __nv_bfloat16*)pw3vl, bv3,
        (const __nv_bfloat16*)pw1kh, (const __nv_bfloat16*)pw1kl, bk1,
        (const __nv_bfloat16*)pw2kh, (const __nv_bfloat16*)pw2kl, bk2,
        (const __nv_bfloat16*)pw3kh, (const __nv_bfloat16*)pw3kl, bk3,
        edge_index, edge_sh);

    attn_agg_kernel<<<(NE + 255) / 256, 256>>>(edge_index);                     // 4
    out_stats_kernel<<<(NN + 63) / 64, 256>>>(node_data, W_output);             // 5
    bn_kernel<<<(NN * 64 + 255) / 256, 256>>>(bn_weight, bn_bias, out);         // 6
}